// round 3
// baseline (speedup 1.0000x reference)
#include <cuda_runtime.h>
#include <math.h>

// ---------------- problem constants ----------------
#define DIMC   1024
#define IMGH   512
#define IMGW   1408
#define CROPP  224
#define NB_B   2
#define NB_NC  6
#define NB_NB  32
#define NN     64          // B*NB
#define NIMG   384         // N*NC
#define CPIX   (224*224)   // 50176

// ---------------- scratch (device globals; no runtime allocs) ----------------
__device__ float g_wT1[147*64];
__device__ float g_wT2[576*256];
__device__ float g_wT3[2304*1024];
__device__ float g_theta[NIMG*6];
__device__ int   g_valid[NIMG];
__device__ float g_crops[(size_t)NIMG*3*CPIX];          // 231 MB
__device__ float g_c1[(size_t)NIMG*64*56*56];           // 308 MB
__device__ float g_c2[(size_t)NIMG*256*14*14];          // 77 MB
__device__ float g_tok[(size_t)NIMG*50*DIMC];           // 79 MB
__device__ float g_q [(size_t)NIMG*DIMC];
__device__ float g_k [(size_t)NIMG*50*DIMC];            // 79 MB
__device__ float g_v [(size_t)NIMG*50*DIMC];            // 79 MB
__device__ float g_av[(size_t)NIMG*DIMC];
__device__ float g_emb[(size_t)NIMG*DIMC];

// 16-wide FMA with transposed-weight row (contiguous 16 floats)
#define FMA16(a, wrow, acc) do {                                              \
    float4 w0_ = __ldg((const float4*)(wrow));                                \
    float4 w1_ = __ldg((const float4*)(wrow)+1);                              \
    float4 w2_ = __ldg((const float4*)(wrow)+2);                              \
    float4 w3_ = __ldg((const float4*)(wrow)+3);                              \
    acc[0]  = fmaf((a), w0_.x, acc[0]);  acc[1]  = fmaf((a), w0_.y, acc[1]);  \
    acc[2]  = fmaf((a), w0_.z, acc[2]);  acc[3]  = fmaf((a), w0_.w, acc[3]);  \
    acc[4]  = fmaf((a), w1_.x, acc[4]);  acc[5]  = fmaf((a), w1_.y, acc[5]);  \
    acc[6]  = fmaf((a), w1_.z, acc[6]);  acc[7]  = fmaf((a), w1_.w, acc[7]);  \
    acc[8]  = fmaf((a), w2_.x, acc[8]);  acc[9]  = fmaf((a), w2_.y, acc[9]);  \
    acc[10] = fmaf((a), w2_.z, acc[10]); acc[11] = fmaf((a), w2_.w, acc[11]); \
    acc[12] = fmaf((a), w3_.x, acc[12]); acc[13] = fmaf((a), w3_.y, acc[13]); \
    acc[14] = fmaf((a), w3_.z, acc[14]); acc[15] = fmaf((a), w3_.w, acc[15]); \
} while (0)

// ---------------- weight transposes (OIHW -> [k][oc]) ----------------
__global__ void k_tr1(const float* w) {
    int i = blockIdx.x*256 + threadIdx.x;
    if (i < 64*147) { int oc = i/147, k = i%147; g_wT1[k*64 + oc] = w[i]; }
}
__global__ void k_tr2(const float* w) {
    int i = blockIdx.x*256 + threadIdx.x;
    if (i < 256*576) { int oc = i/576, k = i%576; g_wT2[k*256 + oc] = w[i]; }
}
__global__ void k_tr3(const float* w) {
    int i = blockIdx.x*256 + threadIdx.x;
    if (i < 1024*2304) { int oc = i/2304, k = i%2304; g_wT3[(size_t)k*1024 + oc] = w[i]; }
}

// ---------------- projection + affine theta ----------------
__global__ void k_theta(const float* boxes, const float* img_aug, const float* lidar_aug,
                        const float* l2i, const float* theta_w, const float* theta_b) {
    int idx = threadIdx.x;           // 0..383 = n*6+c
    if (idx >= NIMG) return;
    int n = idx / NB_NC, c = idx % NB_NC;
    int b = n / NB_NB;
    const float* box = boxes + n*9;
    const float* la  = lidar_aug + b*16;

    float v0 = box[0]-la[3], v1 = box[1]-la[7], v2 = box[2]-la[11];
    float a00=la[0],a01=la[1],a02=la[2],a10=la[4],a11=la[5],a12=la[6],a20=la[8],a21=la[9],a22=la[10];
    float det = a00*(a11*a22-a12*a21) - a01*(a10*a22-a12*a20) + a02*(a10*a21-a11*a20);
    float id  = 1.0f/det;
    float c0 = ((a11*a22-a12*a21)*v0 + (a02*a21-a01*a22)*v1 + (a01*a12-a02*a11)*v2)*id;
    float c1 = ((a12*a20-a10*a22)*v0 + (a00*a22-a02*a20)*v1 + (a02*a10-a00*a12)*v2)*id;
    float c2 = ((a10*a21-a11*a20)*v0 + (a01*a20-a00*a21)*v1 + (a00*a11-a01*a10)*v2)*id;

    const float* M = l2i + (size_t)(b*NB_NC + c)*16;
    float p0 = M[0]*c0 + M[1]*c1 + M[2] *c2 + M[3];
    float p1 = M[4]*c0 + M[5]*c1 + M[6] *c2 + M[7];
    float p2 = M[8]*c0 + M[9]*c1 + M[10]*c2 + M[11];
    float z  = fminf(fmaxf(p2, 1e-5f), 1e5f);
    float x  = p0/z, y = p1/z;
    const float* A = img_aug + (size_t)(b*NB_NC + c)*16;
    float u  = A[0]*x + A[1]*y + A[2]*z + A[3];
    float vv = A[4]*x + A[5]*y + A[6]*z + A[7];
    int on = (vv < (float)IMGH) && (vv >= 0.f) && (u < (float)IMGW) && (u >= 0.f);
    float ty = vv/(float)IMGH*2.f - 1.f;
    float tx = u /(float)IMGW*2.f - 1.f;

    float r[4];
    #pragma unroll
    for (int i = 0; i < 4; i++) {
        float s = theta_b[i];
        #pragma unroll
        for (int j = 0; j < 9; j++) s += box[j]*theta_w[i*9+j];
        r[i] = tanhf(s);
    }
    float* th = g_theta + idx*6;
    th[0]=r[0]; th[1]=r[1]; th[2]=tx; th[3]=r[2]; th[4]=r[3]; th[5]=ty;
    g_valid[idx] = on;
}

// ---------------- affine grid-sample into crops ----------------
__global__ void k_sample(const float* __restrict__ imgs) {
    int img = blockIdx.x;
    int p   = blockIdx.y*256 + threadIdx.x;     // 0..50175
    int h = p / CROPP, w = p % CROPP;
    int n = img / NB_NC, c = img % NB_NC, b = n / NB_NB;
    const float* th = g_theta + img*6;
    float gx = (2.f*w + 1.f)/CROPP - 1.f;
    float gy = (2.f*h + 1.f)/CROPP - 1.f;
    float sx = gx*th[0] + gy*th[1] + th[2];
    float sy = gx*th[3] + gy*th[4] + th[5];
    float ix = ((sx + 1.f)*IMGW - 1.f)*0.5f;
    float iy = ((sy + 1.f)*IMGH - 1.f)*0.5f;
    float x0 = floorf(ix), y0 = floorf(iy);
    float x1 = x0 + 1.f,   y1 = y0 + 1.f;
    float wx = ix - x0,    wy = iy - y0;

    bool vx0 = (x0 >= 0.f) && (x0 <= IMGW-1.f);
    bool vx1 = (x1 >= 0.f) && (x1 <= IMGW-1.f);
    bool vy0 = (y0 >= 0.f) && (y0 <= IMGH-1.f);
    bool vy1 = (y1 >= 0.f) && (y1 <= IMGH-1.f);
    int xi0 = (int)fminf(fmaxf(x0, 0.f), IMGW-1.f);
    int xi1 = (int)fminf(fmaxf(x1, 0.f), IMGW-1.f);
    int yi0 = (int)fminf(fmaxf(y0, 0.f), IMGH-1.f);
    int yi1 = (int)fminf(fmaxf(y1, 0.f), IMGH-1.f);

    float w00 = (1.f-wx)*(1.f-wy), w01 = wx*(1.f-wy);
    float w10 = (1.f-wx)*wy,       w11 = wx*wy;
    const float* base = imgs + ((size_t)(b*NB_NC + c)*3)*IMGH*IMGW;
    #pragma unroll
    for (int ch = 0; ch < 3; ch++) {
        const float* im = base + (size_t)ch*IMGH*IMGW;
        float v00 = (vx0 && vy0) ? im[yi0*IMGW + xi0] : 0.f;
        float v01 = (vx1 && vy0) ? im[yi0*IMGW + xi1] : 0.f;
        float v10 = (vx0 && vy1) ? im[yi1*IMGW + xi0] : 0.f;
        float v11 = (vx1 && vy1) ? im[yi1*IMGW + xi1] : 0.f;
        g_crops[((size_t)img*3 + ch)*CPIX + p] = v00*w00 + v01*w01 + v10*w10 + v11*w11;
    }
}

// ---------------- conv1: 3->64, 7x7, s4, pad(1,2) ----------------
__global__ void k_conv1() {
    __shared__ float sin_[3][7][228];
    int img = blockIdx.x, oy = blockIdx.y;
    int tid = threadIdx.x;  // 224
    for (int j = tid; j < 3*7*228; j += 224) {
        int ci = j / (7*228); int rem = j % (7*228);
        int r = rem / 228, col = rem % 228;
        int iy = 4*oy - 1 + r, sc = col - 1;
        float v = 0.f;
        if (iy >= 0 && iy < 224 && sc >= 0 && sc < 224)
            v = g_crops[((size_t)img*3 + ci)*CPIX + iy*224 + sc];
        sin_[ci][r][col] = v;
    }
    __syncthreads();
    int px = tid % 56, g = tid / 56;   // g 0..3 -> 16 oc each
    float acc[16];
    #pragma unroll
    for (int i = 0; i < 16; i++) acc[i] = 0.f;
    #pragma unroll
    for (int ci = 0; ci < 3; ci++)
        for (int ky = 0; ky < 7; ky++)
            #pragma unroll
            for (int kx = 0; kx < 7; kx++) {
                float a = sin_[ci][ky][4*px + kx];
                const float* wrow = g_wT1 + ((ci*7+ky)*7 + kx)*64 + g*16;
                FMA16(a, wrow, acc);
            }
    size_t basei = ((size_t)img*64 + g*16)*3136 + oy*56 + px;
    #pragma unroll
    for (int j = 0; j < 16; j++) g_c1[basei + (size_t)j*3136] = fmaxf(acc[j], 0.f);
}

// ---------------- conv2: 64->256, 3x3, s4, pad 0 ----------------
__global__ void k_conv2() {
    __shared__ float sin_[64][3][56];     // 43 KB
    int img = blockIdx.x, py = blockIdx.y;
    int tid = threadIdx.x;  // 224
    for (int j = tid; j < 64*3*56; j += 224) {
        int ci = j / 168; int rem = j % 168;
        int r = rem / 56, x = rem % 56;
        sin_[ci][r][x] = g_c1[((size_t)img*64 + ci)*3136 + (4*py + r)*56 + x];
    }
    __syncthreads();
    int px = tid % 14, g = tid / 14;      // g 0..15 -> 16 oc each
    float acc[16];
    #pragma unroll
    for (int i = 0; i < 16; i++) acc[i] = 0.f;
    for (int ci = 0; ci < 64; ci++)
        #pragma unroll
        for (int ky = 0; ky < 3; ky++)
            #pragma unroll
            for (int kx = 0; kx < 3; kx++) {
                float a = sin_[ci][ky][4*px + kx];
                const float* wrow = g_wT2 + (size_t)((ci*3+ky)*3 + kx)*256 + g*16;
                FMA16(a, wrow, acc);
            }
    size_t basei = ((size_t)img*256 + g*16)*196 + py*14 + px;
    #pragma unroll
    for (int j = 0; j < 16; j++) g_c2[basei + (size_t)j*196] = fmaxf(acc[j], 0.f);
}

// ---------------- conv3: 256->1024, 3x3, s2, pad(0,1); writes tokens ----------------
__global__ void k_conv3() {
    __shared__ float sin_[32][15][15];    // 28.8 KB, row/col 14 are zero-pad
    int img = blockIdx.x, occ = blockIdx.y;     // occ 0..7 -> 128 oc
    int tid = threadIdx.x;  // 392
    int p = tid % 49, g = tid / 49;             // g 0..7 -> 16 oc each
    int py = p / 7, px = p % 7;
    int ocbase = occ*128 + g*16;
    float acc[16];
    #pragma unroll
    for (int i = 0; i < 16; i++) acc[i] = 0.f;

    for (int cc = 0; cc < 8; cc++) {
        __syncthreads();
        for (int j = tid; j < 32*225; j += 392) {
            int cil = j / 225; int rem = j % 225;
            int r = rem / 15, x = rem % 15;
            float v = 0.f;
            if (r < 14 && x < 14)
                v = g_c2[((size_t)img*256 + cc*32 + cil)*196 + r*14 + x];
            sin_[cil][r][x] = v;
        }
        __syncthreads();
        for (int cil = 0; cil < 32; cil++)
            #pragma unroll
            for (int ky = 0; ky < 3; ky++)
                #pragma unroll
                for (int kx = 0; kx < 3; kx++) {
                    float a = sin_[cil][2*py + ky][2*px + kx];
                    const float* wrow = g_wT3 + (size_t)(((cc*32+cil)*3+ky)*3 + kx)*1024 + ocbase;
                    FMA16(a, wrow, acc);
                }
    }
    float* dst = g_tok + ((size_t)img*50 + 1 + p)*DIMC + ocbase;
    #pragma unroll
    for (int j = 0; j < 16; j++) dst[j] = fmaxf(acc[j], 0.f);
}

// ---------------- token 0 = mean, add pos_embed ----------------
__global__ void k_tokmean(const float* __restrict__ pos_embed) {
    int img = blockIdx.x, tid = threadIdx.x;   // 256
    float* tb = g_tok + (size_t)img*50*DIMC;
    for (int d = tid; d < DIMC; d += 256) {
        float s = 0.f;
        for (int t = 1; t < 50; t++) s += tb[t*DIMC + d];
        tb[d] = s/49.f + pos_embed[d];
        for (int t = 1; t < 50; t++) tb[t*DIMC + d] += pos_embed[t*DIMC + d];
    }
}

// ---------------- generic 64x64x16 SGEMM (N=1024, K=1024) ----------------
// mode 0: tok@wk->k  1: tok@wv->v  2: tok0@wq->q  3: av@wo->emb
__global__ void k_sgemm(int mode, const float* __restrict__ Bm) {
    __shared__ float As[16][64];
    __shared__ float Bs[16][64];
    const float* A; float* C; int lda;
    if      (mode == 0) { A = g_tok; C = g_k;   lda = 1024;  }
    else if (mode == 1) { A = g_tok; C = g_v;   lda = 1024;  }
    else if (mode == 2) { A = g_tok; C = g_q;   lda = 51200; }
    else                { A = g_av;  C = g_emb; lda = 1024;  }

    int t  = threadIdx.x;
    int tx = t % 16, ty = t / 16;
    int m0 = blockIdx.y*64, n0 = blockIdx.x*64;
    int arow = t / 4,  acol4 = (t % 4)*4;
    int brow = t / 16, bcol4 = (t % 16)*4;
    float acc[4][4];
    #pragma unroll
    for (int i = 0; i < 4; i++)
        #pragma unroll
        for (int j = 0; j < 4; j++) acc[i][j] = 0.f;

    for (int k0 = 0; k0 < 1024; k0 += 16) {
        float4 a4 = __ldg((const float4*)(A + (size_t)(m0+arow)*lda + k0 + acol4));
        As[acol4  ][arow] = a4.x; As[acol4+1][arow] = a4.y;
        As[acol4+2][arow] = a4.z; As[acol4+3][arow] = a4.w;
        float4 b4 = __ldg((const float4*)(Bm + (size_t)(k0+brow)*1024 + n0 + bcol4));
        *(float4*)&Bs[brow][bcol4] = b4;
        __syncthreads();
        #pragma unroll
        for (int kk = 0; kk < 16; kk++) {
            float4 av = *(const float4*)&As[kk][ty*4];
            float4 bv = *(const float4*)&Bs[kk][tx*4];
            acc[0][0] = fmaf(av.x, bv.x, acc[0][0]); acc[0][1] = fmaf(av.x, bv.y, acc[0][1]);
            acc[0][2] = fmaf(av.x, bv.z, acc[0][2]); acc[0][3] = fmaf(av.x, bv.w, acc[0][3]);
            acc[1][0] = fmaf(av.y, bv.x, acc[1][0]); acc[1][1] = fmaf(av.y, bv.y, acc[1][1]);
            acc[1][2] = fmaf(av.y, bv.z, acc[1][2]); acc[1][3] = fmaf(av.y, bv.w, acc[1][3]);
            acc[2][0] = fmaf(av.z, bv.x, acc[2][0]); acc[2][1] = fmaf(av.z, bv.y, acc[2][1]);
            acc[2][2] = fmaf(av.z, bv.z, acc[2][2]); acc[2][3] = fmaf(av.z, bv.w, acc[2][3]);
            acc[3][0] = fmaf(av.w, bv.x, acc[3][0]); acc[3][1] = fmaf(av.w, bv.y, acc[3][1]);
            acc[3][2] = fmaf(av.w, bv.z, acc[3][2]); acc[3][3] = fmaf(av.w, bv.w, acc[3][3]);
        }
        __syncthreads();
    }
    #pragma unroll
    for (int i = 0; i < 4; i++)
        #pragma unroll
        for (int j = 0; j < 4; j++)
            C[(size_t)(m0 + ty*4 + i)*1024 + n0 + tx*4 + j] = acc[i][j];
}

// ---------------- attention (per image) ----------------
__global__ void k_attn() {
    __shared__ float qs[1024];
    __shared__ float ps[50];
    int img = blockIdx.x, tid = threadIdx.x;   // 256
    for (int d = tid; d < 1024; d += 256) qs[d] = g_q[(size_t)img*1024 + d];
    __syncthreads();
    int w = tid / 32, lane = tid % 32;
    for (int t = w; t < 50; t += 8) {
        const float* kr = g_k + ((size_t)img*50 + t)*1024;
        float s = 0.f;
        for (int d = lane; d < 1024; d += 32) s += qs[d]*kr[d];
        #pragma unroll
        for (int o = 16; o; o >>= 1) s += __shfl_xor_sync(0xffffffffu, s, o);
        if (lane == 0) ps[t] = s*0.03125f;
    }
    __syncthreads();
    if (tid == 0) {
        float mx = -1e30f;
        for (int t = 0; t < 50; t++) mx = fmaxf(mx, ps[t]);
        float den = 0.f;
        for (int t = 0; t < 50; t++) { float e = expf(ps[t]-mx); ps[t] = e; den += e; }
        float inv = 1.f/den;
        for (int t = 0; t < 50; t++) ps[t] *= inv;
    }
    __syncthreads();
    for (int d = tid; d < 1024; d += 256) {
        float s = 0.f;
        for (int t = 0; t < 50; t++) s += ps[t]*g_v[((size_t)img*50 + t)*1024 + d];
        g_av[(size_t)img*1024 + d] = s;
    }
}

// ---------------- EMA over cameras ----------------
__global__ void k_ema(const float* __restrict__ box_default, const float* __restrict__ momentum,
                      float* __restrict__ out) {
    int idx = blockIdx.x*256 + threadIdx.x;
    if (idx >= NN*DIMC) return;
    int n = idx >> 10, d = idx & 1023;
    float m = *momentum;
    float e = box_default[d];
    const int order[6] = {2,0,1,5,3,4};
    #pragma unroll
    for (int i = 0; i < 6; i++) {
        int c = order[i];
        if (g_valid[n*6 + c]) e = m*e + (1.f - m)*g_emb[((size_t)(n*6 + c))*1024 + d];
    }
    out[idx] = e;
}

// ---------------- launch ----------------
extern "C" void kernel_launch(void* const* d_in, const int* in_sizes, int n_in,
                              void* d_out, int out_size) {
    const float* imgs       = (const float*)d_in[0];
    const float* boxes      = (const float*)d_in[1];
    const float* img_aug    = (const float*)d_in[2];
    const float* lidar_aug  = (const float*)d_in[3];
    const float* l2i        = (const float*)d_in[4];
    const float* momentum   = (const float*)d_in[5];
    const float* box_def    = (const float*)d_in[6];
    const float* theta_w    = (const float*)d_in[7];
    const float* theta_b    = (const float*)d_in[8];
    const float* conv1w     = (const float*)d_in[9];
    const float* conv2w     = (const float*)d_in[10];
    const float* conv3w     = (const float*)d_in[11];
    const float* pos_embed  = (const float*)d_in[12];
    const float* wq         = (const float*)d_in[13];
    const float* wk         = (const float*)d_in[14];
    const float* wv         = (const float*)d_in[15];
    const float* wo         = (const float*)d_in[16];
    float* out = (float*)d_out;

    k_tr1<<<(64*147 + 255)/256, 256>>>(conv1w);
    k_tr2<<<(256*576 + 255)/256, 256>>>(conv2w);
    k_tr3<<<(1024*2304 + 255)/256, 256>>>(conv3w);
    k_theta<<<1, 384>>>(boxes, img_aug, lidar_aug, l2i, theta_w, theta_b);
    k_sample<<<dim3(NIMG, CPIX/256), 256>>>(imgs);
    k_conv1<<<dim3(NIMG, 56), 224>>>();
    k_conv2<<<dim3(NIMG, 14), 224>>>();
    k_conv3<<<dim3(NIMG, 8), 392>>>();
    k_tokmean<<<NIMG, 256>>>(pos_embed);
    k_sgemm<<<dim3(16, 300), 256>>>(0, wk);
    k_sgemm<<<dim3(16, 300), 256>>>(1, wv);
    k_sgemm<<<dim3(16, 6),   256>>>(2, wq);
    k_attn<<<NIMG, 256>>>();
    k_sgemm<<<dim3(16, 6),   256>>>(3, wo);
    k_ema<<<(NN*DIMC + 255)/256, 256>>>(box_def, momentum, out);
}

// round 6
// speedup vs baseline: 3.3047x; 3.3047x over previous
#include <cuda_runtime.h>
#include <cuda_bf16.h>
#include <cstdint>
#include <math.h>

// ---------------- problem constants ----------------
#define DIMC   1024
#define IMGH   512
#define IMGW   1408
#define CROPP  224
#define NB_NC  6
#define NB_NB  32
#define NN     64          // B*NB
#define NIMG   384         // N*NC
#define CPIX   (224*224)   // 50176

// GEMM shapes (all exact multiples of 128 / 64)
#define M1 1204224         // conv1 rows = 384*56*56   (9408 tiles)
#define K1 192             // 147 padded to 192
#define M2 75264           // conv2 rows = 384*14*14   (588 tiles)
#define K2 576
#define M3 18816           // conv3 rows = 384*7*7     (147 tiles)
#define K3 2304
#define MKV 19200          // 384*50                   (150 tiles)
#define KKV 1024

// ---------------- scratch (device globals; no runtime allocs) ----------------
#define A1LO  ((size_t)M1*K1*2)            // 462,422,016
#define A23LO ((size_t)M2*K2*2)            //  86,704,128  (== M3*K3*2)
#define TOKLO ((size_t)MKV*KKV*2)          //  39,321,600
__device__ __align__(256) char g_arena[(size_t)M1*K1*2*2];   // 925 MB

__device__ float g_theta[NIMG*6];
__device__ int   g_valid[NIMG];
__device__ float g_crops[(size_t)NIMG*3*CPIX];     // 231 MB
__device__ float g_c1rm [(size_t)M1*64];           // 308 MB  [row][oc]
__device__ float g_c2rm [(size_t)M2*256];          // 77 MB   [row][oc]
__device__ float g_tok  [(size_t)NIMG*50*DIMC];    // 79 MB
__device__ float g_kv   [(size_t)MKV*2048];        // 157 MB  k | v
__device__ float g_q    [(size_t)NIMG*DIMC];
__device__ float g_av   [(size_t)NIMG*DIMC];
__device__ float g_emb  [(size_t)NIMG*DIMC];

// bf16 weight matrices, row-major [n][k]
__device__ __nv_bfloat16 g_B1h[128*K1],   g_B1l[128*K1];
__device__ __nv_bfloat16 g_B2h[256*K2],   g_B2l[256*K2];
__device__ __nv_bfloat16 g_B3h[1024*K3],  g_B3l[1024*K3];
__device__ __nv_bfloat16 g_Bkvh[2048*KKV], g_Bkvl[2048*KKV];

// ---------------- helpers ----------------
__device__ __forceinline__ uint32_t smem_u32(const void* p) {
    uint32_t a;
    asm("{ .reg .u64 t; cvta.to.shared.u64 t, %1; cvt.u32.u64 %0, t; }" : "=r"(a) : "l"(p));
    return a;
}
__device__ __forceinline__ void bsplit(float v, __nv_bfloat16* hi, __nv_bfloat16* lo, size_t i) {
    __nv_bfloat16 h = __float2bfloat16(v);
    hi[i] = h;
    lo[i] = __float2bfloat16(v - __bfloat162float(h));
}
__device__ __forceinline__ void ldm4(uint32_t& r0, uint32_t& r1, uint32_t& r2, uint32_t& r3, uint32_t addr) {
    asm volatile("ldmatrix.sync.aligned.m8n8.x4.shared.b16 {%0,%1,%2,%3}, [%4];"
                 : "=r"(r0), "=r"(r1), "=r"(r2), "=r"(r3) : "r"(addr));
}
__device__ __forceinline__ void mma16816(float* d, const uint32_t* a, const uint32_t* b) {
    asm volatile("mma.sync.aligned.m16n8k16.row.col.f32.bf16.bf16.f32 "
                 "{%0,%1,%2,%3}, {%4,%5,%6,%7}, {%8,%9}, {%0,%1,%2,%3};"
                 : "+f"(d[0]), "+f"(d[1]), "+f"(d[2]), "+f"(d[3])
                 : "r"(a[0]), "r"(a[1]), "r"(a[2]), "r"(a[3]), "r"(b[0]), "r"(b[1]));
}

// ---------------- projection + affine theta ----------------
__global__ void k_theta(const float* boxes, const float* img_aug, const float* lidar_aug,
                        const float* l2i, const float* theta_w, const float* theta_b) {
    int idx = threadIdx.x;
    if (idx >= NIMG) return;
    int n = idx / NB_NC, c = idx % NB_NC;
    int b = n / NB_NB;
    const float* box = boxes + n*9;
    const float* la  = lidar_aug + b*16;

    float v0 = box[0]-la[3], v1 = box[1]-la[7], v2 = box[2]-la[11];
    float a00=la[0],a01=la[1],a02=la[2],a10=la[4],a11=la[5],a12=la[6],a20=la[8],a21=la[9],a22=la[10];
    float det = a00*(a11*a22-a12*a21) - a01*(a10*a22-a12*a20) + a02*(a10*a21-a11*a20);
    float id  = 1.0f/det;
    float c0 = ((a11*a22-a12*a21)*v0 + (a02*a21-a01*a22)*v1 + (a01*a12-a02*a11)*v2)*id;
    float c1 = ((a12*a20-a10*a22)*v0 + (a00*a22-a02*a20)*v1 + (a02*a10-a00*a12)*v2)*id;
    float c2 = ((a10*a21-a11*a20)*v0 + (a01*a20-a00*a21)*v1 + (a00*a11-a01*a10)*v2)*id;

    const float* M = l2i + (size_t)(b*NB_NC + c)*16;
    float p0 = M[0]*c0 + M[1]*c1 + M[2] *c2 + M[3];
    float p1 = M[4]*c0 + M[5]*c1 + M[6] *c2 + M[7];
    float p2 = M[8]*c0 + M[9]*c1 + M[10]*c2 + M[11];
    float z  = fminf(fmaxf(p2, 1e-5f), 1e5f);
    float x  = p0/z, y = p1/z;
    const float* A = img_aug + (size_t)(b*NB_NC + c)*16;
    float u  = A[0]*x + A[1]*y + A[2]*z + A[3];
    float vv = A[4]*x + A[5]*y + A[6]*z + A[7];
    int on = (vv < (float)IMGH) && (vv >= 0.f) && (u < (float)IMGW) && (u >= 0.f);
    float ty = vv/(float)IMGH*2.f - 1.f;
    float tx = u /(float)IMGW*2.f - 1.f;

    float r[4];
    #pragma unroll
    for (int i = 0; i < 4; i++) {
        float s = theta_b[i];
        #pragma unroll
        for (int j = 0; j < 9; j++) s += box[j]*theta_w[i*9+j];
        r[i] = tanhf(s);
    }
    float* th = g_theta + idx*6;
    th[0]=r[0]; th[1]=r[1]; th[2]=tx; th[3]=r[2]; th[4]=r[3]; th[5]=ty;
    g_valid[idx] = on;
}

// ---------------- affine grid-sample into crops ----------------
__global__ void k_sample(const float* __restrict__ imgs) {
    int img = blockIdx.x;
    int p   = blockIdx.y*256 + threadIdx.x;
    int h = p / CROPP, w = p % CROPP;
    int n = img / NB_NC, c = img % NB_NC, b = n / NB_NB;
    const float* th = g_theta + img*6;
    float gx = (2.f*w + 1.f)/CROPP - 1.f;
    float gy = (2.f*h + 1.f)/CROPP - 1.f;
    float sx = gx*th[0] + gy*th[1] + th[2];
    float sy = gx*th[3] + gy*th[4] + th[5];
    float ix = ((sx + 1.f)*IMGW - 1.f)*0.5f;
    float iy = ((sy + 1.f)*IMGH - 1.f)*0.5f;
    float x0 = floorf(ix), y0 = floorf(iy);
    float x1 = x0 + 1.f,   y1 = y0 + 1.f;
    float wx = ix - x0,    wy = iy - y0;

    bool vx0 = (x0 >= 0.f) && (x0 <= IMGW-1.f);
    bool vx1 = (x1 >= 0.f) && (x1 <= IMGW-1.f);
    bool vy0 = (y0 >= 0.f) && (y0 <= IMGH-1.f);
    bool vy1 = (y1 >= 0.f) && (y1 <= IMGH-1.f);
    int xi0 = (int)fminf(fmaxf(x0, 0.f), IMGW-1.f);
    int xi1 = (int)fminf(fmaxf(x1, 0.f), IMGW-1.f);
    int yi0 = (int)fminf(fmaxf(y0, 0.f), IMGH-1.f);
    int yi1 = (int)fminf(fmaxf(y1, 0.f), IMGH-1.f);

    float w00 = (1.f-wx)*(1.f-wy), w01 = wx*(1.f-wy);
    float w10 = (1.f-wx)*wy,       w11 = wx*wy;
    const float* base = imgs + ((size_t)(b*NB_NC + c)*3)*IMGH*IMGW;
    #pragma unroll
    for (int ch = 0; ch < 3; ch++) {
        const float* im = base + (size_t)ch*IMGH*IMGW;
        float v00 = (vx0 && vy0) ? im[yi0*IMGW + xi0] : 0.f;
        float v01 = (vx1 && vy0) ? im[yi0*IMGW + xi1] : 0.f;
        float v10 = (vx0 && vy1) ? im[yi1*IMGW + xi0] : 0.f;
        float v11 = (vx1 && vy1) ? im[yi1*IMGW + xi1] : 0.f;
        g_crops[((size_t)img*3 + ch)*CPIX + p] = v00*w00 + v01*w01 + v10*w10 + v11*w11;
    }
}

// ---------------- weight bf16 hi/lo splits ----------------
__global__ void k_split_w1(const float* __restrict__ w) {  // conv1 [64][147] -> [128][192] padded
    int i = blockIdx.x*256 + threadIdx.x;
    if (i >= 128*K1) return;
    int n = i / K1, k = i % K1;
    float v = (n < 64 && k < 147) ? w[n*147 + k] : 0.f;
    bsplit(v, g_B1h, g_B1l, i);
}
__global__ void k_split_w2(const float* __restrict__ w) {  // [256][576] direct
    int i = blockIdx.x*256 + threadIdx.x;
    if (i >= 256*K2) return;
    bsplit(w[i], g_B2h, g_B2l, i);
}
__global__ void k_split_w3(const float* __restrict__ w) {  // [1024][2304] direct
    int i = blockIdx.x*256 + threadIdx.x;
    if (i >= 1024*K3) return;
    bsplit(w[i], g_B3h, g_B3l, i);
}
__global__ void k_split_wkv(const float* __restrict__ wk, const float* __restrict__ wv) {
    int i = blockIdx.x*256 + threadIdx.x;          // [2048][1024], B[n][k] = w[k][n]
    if (i >= 2048*KKV) return;
    int n = i / KKV, k = i % KKV;
    float v = (n < 1024) ? wk[k*1024 + n] : wv[k*1024 + (n - 1024)];
    bsplit(v, g_Bkvh, g_Bkvl, i);
}
__global__ void k_split_tok() {                    // tok -> arena hi/lo
    size_t i = (size_t)blockIdx.x*256 + threadIdx.x;
    if (i >= (size_t)MKV*KKV) return;
    bsplit(g_tok[i], (__nv_bfloat16*)g_arena, (__nv_bfloat16*)(g_arena + TOKLO), i);
}

// ---------------- im2col builders (write bf16 hi/lo into arena) ----------------
__global__ void k_im2col1() {   // from g_crops; conv1 7x7 s4 pad(1,2); K padded 147->192
    size_t i = (size_t)blockIdx.x*256 + threadIdx.x;
    if (i >= (size_t)M1*K1) return;
    int k = (int)(i % K1); size_t row = i / K1;
    int img = (int)(row / 3136); int p = (int)(row % 3136);
    int oy = p / 56, ox = p % 56;
    float v = 0.f;
    if (k < 147) {
        int ci = k / 49, r = (k % 49) / 7, s = k % 7;
        int iy = 4*oy - 1 + r, ix = 4*ox - 1 + s;
        if (iy >= 0 && iy < 224 && ix >= 0 && ix < 224)
            v = g_crops[((size_t)img*3 + ci)*CPIX + iy*224 + ix];
    }
    bsplit(v, (__nv_bfloat16*)g_arena, (__nv_bfloat16*)(g_arena + A1LO), i);
}
__global__ void k_im2col2() {   // from g_c1rm; conv2 3x3 s4 pad0
    size_t i = (size_t)blockIdx.x*256 + threadIdx.x;
    if (i >= (size_t)M2*K2) return;
    int k = (int)(i % K2); size_t row = i / K2;
    int img = (int)(row / 196); int p = (int)(row % 196);
    int py = p / 14, px = p % 14;
    int ci = k / 9, r = (k % 9) / 3, s = k % 3;
    int iy = 4*py + r, ix = 4*px + s;
    float v = g_c1rm[((size_t)img*3136 + iy*56 + ix)*64 + ci];
    bsplit(v, (__nv_bfloat16*)g_arena, (__nv_bfloat16*)(g_arena + A23LO), i);
}
__global__ void k_im2col3() {   // from g_c2rm; conv3 3x3 s2 pad(0,1)
    size_t i = (size_t)blockIdx.x*256 + threadIdx.x;
    if (i >= (size_t)M3*K3) return;
    int k = (int)(i % K3); size_t row = i / K3;
    int img = (int)(row / 49); int p = (int)(row % 49);
    int py = p / 7, px = p % 7;
    int ci = k / 9, r = (k % 9) / 3, s = k % 3;
    int iy = 2*py + r, ix = 2*px + s;
    float v = (iy < 14 && ix < 14) ? g_c2rm[((size_t)img*196 + iy*14 + ix)*256 + ci] : 0.f;
    bsplit(v, (__nv_bfloat16*)g_arena, (__nv_bfloat16*)(g_arena + A23LO), i);
}

// ---------------- warp-MMA bf16x3 GEMM: C[M,N] = A @ B^T ----------------
// Block 128x128, 8 warps of 64x32, K-chunk 64, SW128 swizzle + ldmatrix.
// Accumulates all 3 compensation passes in registers.
// which 0: conv1   1: conv2   2: conv3 (->tok rows)   3: K|V
__global__ void __launch_bounds__(256) k_mma_gemm(int which) {
    __shared__ __align__(1024) __nv_bfloat16 sA[128*64];
    __shared__ __align__(1024) __nv_bfloat16 sB[128*64];

    const __nv_bfloat16 *Ah, *Al, *Bh, *Bl; float* C;
    int K, ldc, relu, rmap, nwr;
    if (which == 0) {
        Ah = (const __nv_bfloat16*)g_arena; Al = (const __nv_bfloat16*)(g_arena + A1LO);
        Bh = g_B1h; Bl = g_B1l; C = g_c1rm; K = K1; ldc = 64;  relu = 1; rmap = 0; nwr = 64;
    } else if (which == 1) {
        Ah = (const __nv_bfloat16*)g_arena; Al = (const __nv_bfloat16*)(g_arena + A23LO);
        Bh = g_B2h; Bl = g_B2l; C = g_c2rm; K = K2; ldc = 256; relu = 1; rmap = 0; nwr = 128;
    } else if (which == 2) {
        Ah = (const __nv_bfloat16*)g_arena; Al = (const __nv_bfloat16*)(g_arena + A23LO);
        Bh = g_B3h; Bl = g_B3l; C = g_tok;  K = K3; ldc = 1024; relu = 1; rmap = 1; nwr = 128;
    } else {
        Ah = (const __nv_bfloat16*)g_arena; Al = (const __nv_bfloat16*)(g_arena + TOKLO);
        Bh = g_Bkvh; Bl = g_Bkvl; C = g_kv; K = KKV; ldc = 2048; relu = 0; rmap = 0; nwr = 128;
    }

    int tid  = threadIdx.x;
    int wid  = tid >> 5, lane = tid & 31;
    int m0 = blockIdx.y*128, n0 = blockIdx.x*128;
    int wm0 = (wid >> 2)*64, wn0 = (wid & 3)*32;

    uint32_t sAb = smem_u32(sA), sBb = smem_u32(sB);

    // loader mapping: 1024 16B chunks per tile; thread t handles chunks t+256*i
    int lrow0 = tid >> 3;              // rows 0..31 (+32 per i)
    int lc    = tid & 7;               // logical chunk 0..7

    // ldmatrix lane addressing (A and B identical form)
    int frow = lane & 15;              // row within 16-row frag
    int fcofs = lane >> 4;             // chunk offset 0/1

    float acc[4][4][4];
    #pragma unroll
    for (int mf = 0; mf < 4; mf++)
        #pragma unroll
        for (int nf = 0; nf < 4; nf++)
            #pragma unroll
            for (int e = 0; e < 4; e++) acc[mf][nf][e] = 0.f;

    int KB = K >> 6;
    for (int ps = 0; ps < 3; ps++) {
        const __nv_bfloat16* Ap = (ps == 2) ? Al : Ah;
        const __nv_bfloat16* Bp = (ps == 1) ? Bl : Bh;
        for (int kb = 0; kb < KB; kb++) {
            int k0 = kb << 6;
            __syncthreads();
            #pragma unroll
            for (int i = 0; i < 4; i++) {
                int r = lrow0 + 32*i;
                int swc = lc ^ (r & 7);
                uint32_t soff = (uint32_t)(r*128 + swc*16);
                *(float4*)((char*)sA + soff) = __ldg((const float4*)(Ap + (size_t)(m0 + r)*K + k0 + lc*8));
                *(float4*)((char*)sB + soff) = __ldg((const float4*)(Bp + (size_t)(n0 + r)*K + k0 + lc*8));
            }
            __syncthreads();

            #pragma unroll
            for (int kf = 0; kf < 4; kf++) {
                uint32_t af[4][4], bf[4][2];
                #pragma unroll
                for (int mf = 0; mf < 4; mf++) {
                    int r = wm0 + mf*16 + frow;
                    int ch = (2*kf + fcofs) ^ (r & 7);
                    ldm4(af[mf][0], af[mf][1], af[mf][2], af[mf][3], sAb + r*128 + ch*16);
                }
                #pragma unroll
                for (int ng = 0; ng < 2; ng++) {
                    int r = wn0 + ng*16 + frow;
                    int ch = (2*kf + fcofs) ^ (r & 7);
                    uint32_t r0, r1, r2, r3;
                    ldm4(r0, r1, r2, r3, sBb + r*128 + ch*16);
                    bf[2*ng][0] = r0;   bf[2*ng][1] = r2;
                    bf[2*ng+1][0] = r1; bf[2*ng+1][1] = r3;
                }
                #pragma unroll
                for (int mf = 0; mf < 4; mf++)
                    #pragma unroll
                    for (int nf = 0; nf < 4; nf++)
                        mma16816(acc[mf][nf], af[mf], bf[nf]);
            }
        }
    }

    // epilogue: C frag mapping: c0,c1 -> (row q, col 2p..2p+1), c2,c3 -> (row q+8)
    int q = lane >> 2, pp = 2*(lane & 3);
    #pragma unroll
    for (int mf = 0; mf < 4; mf++) {
        #pragma unroll
        for (int h = 0; h < 2; h++) {
            int m = m0 + wm0 + mf*16 + q + 8*h;
            size_t orow;
            if (rmap) { int img = m / 49, p = m % 49; orow = (size_t)img*50 + 1 + p; }
            else orow = (size_t)m;
            float* dst = C + orow*(size_t)ldc;
            #pragma unroll
            for (int nf = 0; nf < 4; nf++) {
                int col = wn0 + nf*8;
                if (col >= nwr) continue;
                float v0 = acc[mf][nf][2*h + 0];
                float v1 = acc[mf][nf][2*h + 1];
                if (relu) { v0 = fmaxf(v0, 0.f); v1 = fmaxf(v1, 0.f); }
                *(float2*)(dst + n0 + col + pp) = make_float2(v0, v1);
            }
        }
    }
}

// ---------------- token 0 = mean, add pos_embed ----------------
__global__ void k_tokmean(const float* __restrict__ pos_embed) {
    int img = blockIdx.x, tid = threadIdx.x;
    float* tb = g_tok + (size_t)img*50*DIMC;
    for (int d = tid; d < DIMC; d += 256) {
        float s = 0.f;
        for (int t = 1; t < 50; t++) s += tb[t*DIMC + d];
        tb[d] = s/49.f + pos_embed[d];
        for (int t = 1; t < 50; t++) tb[t*DIMC + d] += pos_embed[t*DIMC + d];
    }
}

// ---------------- small fp32 SGEMM for q / o (384x1024x1024 each) ----------------
__global__ void k_sgemm(int mode, const float* __restrict__ Bm) {
    __shared__ float As[16][64];
    __shared__ float Bs[16][64];
    const float* A; float* C; int lda;
    if (mode == 0) { A = g_tok; C = g_q;   lda = 51200; }
    else           { A = g_av;  C = g_emb; lda = 1024;  }

    int t  = threadIdx.x;
    int tx = t % 16, ty = t / 16;
    int m0 = blockIdx.y*64, n0 = blockIdx.x*64;
    int arow = t / 4,  acol4 = (t % 4)*4;
    int brow = t / 16, bcol4 = (t % 16)*4;
    float acc[4][4];
    #pragma unroll
    for (int i = 0; i < 4; i++)
        #pragma unroll
        for (int j = 0; j < 4; j++) acc[i][j] = 0.f;

    for (int k0 = 0; k0 < 1024; k0 += 16) {
        float4 a4 = __ldg((const float4*)(A + (size_t)(m0+arow)*lda + k0 + acol4));
        As[acol4  ][arow] = a4.x; As[acol4+1][arow] = a4.y;
        As[acol4+2][arow] = a4.z; As[acol4+3][arow] = a4.w;
        float4 b4 = __ldg((const float4*)(Bm + (size_t)(k0+brow)*1024 + n0 + bcol4));
        *(float4*)&Bs[brow][bcol4] = b4;
        __syncthreads();
        #pragma unroll
        for (int kk = 0; kk < 16; kk++) {
            float4 av = *(const float4*)&As[kk][ty*4];
            float4 bv = *(const float4*)&Bs[kk][tx*4];
            acc[0][0] = fmaf(av.x, bv.x, acc[0][0]); acc[0][1] = fmaf(av.x, bv.y, acc[0][1]);
            acc[0][2] = fmaf(av.x, bv.z, acc[0][2]); acc[0][3] = fmaf(av.x, bv.w, acc[0][3]);
            acc[1][0] = fmaf(av.y, bv.x, acc[1][0]); acc[1][1] = fmaf(av.y, bv.y, acc[1][1]);
            acc[1][2] = fmaf(av.y, bv.z, acc[1][2]); acc[1][3] = fmaf(av.y, bv.w, acc[1][3]);
            acc[2][0] = fmaf(av.z, bv.x, acc[2][0]); acc[2][1] = fmaf(av.z, bv.y, acc[2][1]);
            acc[2][2] = fmaf(av.z, bv.z, acc[2][2]); acc[2][3] = fmaf(av.z, bv.w, acc[2][3]);
            acc[3][0] = fmaf(av.w, bv.x, acc[3][0]); acc[3][1] = fmaf(av.w, bv.y, acc[3][1]);
            acc[3][2] = fmaf(av.w, bv.z, acc[3][2]); acc[3][3] = fmaf(av.w, bv.w, acc[3][3]);
        }
        __syncthreads();
    }
    #pragma unroll
    for (int i = 0; i < 4; i++)
        #pragma unroll
        for (int j = 0; j < 4; j++)
            C[(size_t)(m0 + ty*4 + i)*1024 + n0 + tx*4 + j] = acc[i][j];
}

// ---------------- attention (per image) ----------------
__global__ void k_attn() {
    __shared__ float qs[1024];
    __shared__ float ps[50];
    int img = blockIdx.x, tid = threadIdx.x;
    for (int d = tid; d < 1024; d += 256) qs[d] = g_q[(size_t)img*1024 + d];
    __syncthreads();
    int w = tid / 32, lane = tid % 32;
    for (int t = w; t < 50; t += 8) {
        const float* kr = g_kv + ((size_t)img*50 + t)*2048;
        float s = 0.f;
        for (int d = lane; d < 1024; d += 32) s += qs[d]*kr[d];
        #pragma unroll
        for (int o = 16; o; o >>= 1) s += __shfl_xor_sync(0xffffffffu, s, o);
        if (lane == 0) ps[t] = s*0.03125f;
    }
    __syncthreads();
    if (tid == 0) {
        float mx = -1e30f;
        for (int t = 0; t < 50; t++) mx = fmaxf(mx, ps[t]);
        float den = 0.f;
        for (int t = 0; t < 50; t++) { float e = expf(ps[t]-mx); ps[t] = e; den += e; }
        float inv = 1.f/den;
        for (int t = 0; t < 50; t++) ps[t] *= inv;
    }
    __syncthreads();
    for (int d = tid; d < 1024; d += 256) {
        float s = 0.f;
        for (int t = 0; t < 50; t++) s += ps[t]*g_kv[((size_t)img*50 + t)*2048 + 1024 + d];
        g_av[(size_t)img*1024 + d] = s;
    }
}

// ---------------- EMA over cameras ----------------
__global__ void k_ema(const float* __restrict__ box_default, const float* __restrict__ momentum,
                      float* __restrict__ out) {
    int idx = blockIdx.x*256 + threadIdx.x;
    if (idx >= NN*DIMC) return;
    int n = idx >> 10, d = idx & 1023;
    float m = *momentum;
    float e = box_default[d];
    const int order[6] = {2,0,1,5,3,4};
    #pragma unroll
    for (int i = 0; i < 6; i++) {
        int c = order[i];
        if (g_valid[n*6 + c]) e = m*e + (1.f - m)*g_emb[((size_t)(n*6 + c))*1024 + d];
    }
    out[idx] = e;
}

// ---------------- launch ----------------
extern "C" void kernel_launch(void* const* d_in, const int* in_sizes, int n_in,
                              void* d_out, int out_size) {
    const float* imgs       = (const float*)d_in[0];
    const float* boxes      = (const float*)d_in[1];
    const float* img_aug    = (const float*)d_in[2];
    const float* lidar_aug  = (const float*)d_in[3];
    const float* l2i        = (const float*)d_in[4];
    const float* momentum   = (const float*)d_in[5];
    const float* box_def    = (const float*)d_in[6];
    const float* theta_w    = (const float*)d_in[7];
    const float* theta_b    = (const float*)d_in[8];
    const float* conv1w     = (const float*)d_in[9];
    const float* conv2w     = (const float*)d_in[10];
    const float* conv3w     = (const float*)d_in[11];
    const float* pos_embed  = (const float*)d_in[12];
    const float* wq         = (const float*)d_in[13];
    const float* wk         = (const float*)d_in[14];
    const float* wv         = (const float*)d_in[15];
    const float* wo         = (const float*)d_in[16];
    float* out = (float*)d_out;

    k_theta<<<1, 384>>>(boxes, img_aug, lidar_aug, l2i, theta_w, theta_b);
    k_sample<<<dim3(NIMG, CPIX/256), 256>>>(imgs);

    k_split_w1 <<<(128*K1   + 255)/256, 256>>>(conv1w);
    k_split_w2 <<<(256*K2   + 255)/256, 256>>>(conv2w);
    k_split_w3 <<<(1024*K3  + 255)/256, 256>>>(conv3w);
    k_split_wkv<<<(2048*KKV + 255)/256, 256>>>(wk, wv);

    k_im2col1<<<(unsigned)(((size_t)M1*K1 + 255)/256), 256>>>();
    k_mma_gemm<<<dim3(1, M1/128), 256>>>(0);           // conv1 -> c1_rm
    k_im2col2<<<(unsigned)(((size_t)M2*K2 + 255)/256), 256>>>();
    k_mma_gemm<<<dim3(2, M2/128), 256>>>(1);           // conv2 -> c2_rm
    k_im2col3<<<(unsigned)(((size_t)M3*K3 + 255)/256), 256>>>();
    k_mma_gemm<<<dim3(8, M3/128), 256>>>(2);           // conv3 -> tok[1..49]

    k_tokmean<<<NIMG, 256>>>(pos_embed);
    k_split_tok<<<(unsigned)(((size_t)MKV*KKV + 255)/256), 256>>>();
    k_mma_gemm<<<dim3(16, MKV/128), 256>>>(3);         // K|V -> g_kv

    k_sgemm<<<dim3(16, 6), 256>>>(0, wq);
    k_attn<<<NIMG, 256>>>();
    k_sgemm<<<dim3(16, 6), 256>>>(1, wo);
    k_ema<<<(NN*DIMC + 255)/256, 256>>>(box_def, momentum, out);
}